// round 6
// baseline (speedup 1.0000x reference)
#include <cuda_runtime.h>

#define BB 64
#define NN 65536
#define RADIUS 0.2f

// Scratch (__device__ globals per allocation-free rule)
__device__ float    g_pval[3][BB * 64];             // argmax partials per FPS step
__device__ int      g_pidx[3][BB * 64];
__device__ unsigned g_bm[BB * (NN / 32)];           // keep bitmask, 512 KB
__device__ int      g_cnt[BB * 32];                 // per-chunk keep counts
__device__ int      g_numvalid[BB];
__device__ int      g_kept[(size_t)BB * NN];        // stable kept indices, 16 MB

// ---------------------------------------------------------------------------
// Argmax helpers: larger value wins, tie -> smaller index (jnp.argmax semantics)
// ---------------------------------------------------------------------------
__device__ __forceinline__ void warp_argmax(float& v, int& i) {
    #pragma unroll
    for (int off = 16; off; off >>= 1) {
        float ov = __shfl_down_sync(0xffffffffu, v, off);
        int   oi = __shfl_down_sync(0xffffffffu, i, off);
        if (ov > v || (ov == v && oi < i)) { v = ov; i = oi; }
    }
}

// 256-thread (8-warp) block argmax; result valid in thread 0.
__device__ __forceinline__ void block_argmax256(float& v, int& i, int tid,
                                                float* s_val, int* s_idx) {
    warp_argmax(v, i);
    if ((tid & 31) == 0) { s_val[tid >> 5] = v; s_idx[tid >> 5] = i; }
    __syncthreads();
    if (tid < 32) {
        v = (tid < 8) ? s_val[tid] : -2.0f;
        i = (tid < 8) ? s_idx[tid] : NN;
        warp_argmax(v, i);
    }
}

// Reduce 64 partials of set j -> argmax (lane 0 of calling warp holds result).
__device__ __forceinline__ void reduce_partials(int j, int b, int lane,
                                                float& v, int& i) {
    v = g_pval[j][b * 64 + lane];
    i = g_pidx[j][b * 64 + lane];
    float v2 = g_pval[j][b * 64 + 32 + lane];
    int   i2 = g_pidx[j][b * 64 + 32 + lane];
    if (v2 > v || (v2 == v && i2 < i)) { v = v2; i = i2; }
    warp_argmax(v, i);
}

// Load xyz of point p in batch base (stride-6 layout). 24B stride, 8-aligned.
__device__ __forceinline__ float3 load_xyz(const float* __restrict__ base, int p) {
    const float* q = base + (size_t)p * 6;
    float2 xy = *(const float2*)q;
    return make_float3(xy.x, xy.y, q[2]);
}

// Recover centers 1..S-1 into sc[] (center 0 = point 0). Call with full block.
template <int S>
__device__ __forceinline__ void recover_centers(const float* __restrict__ base,
                                                int b, int tid, float3* sc) {
    if (tid == 0) sc[0] = load_xyz(base, 0);
    if (tid < 32) {
        #pragma unroll
        for (int j = 0; j < S - 1; j++) {
            float v; int i;
            reduce_partials(j, b, tid, v, i);
            if (tid == 0) sc[j + 1] = load_xyz(base, i);
        }
    }
    __syncthreads();
}

// ---------------------------------------------------------------------------
// K1..K3: FPS sweep with S known centers (S=1,2,3), reading pts directly.
// grid (64, BB) x 256; 1024 pts/block. S=1 warms L2 with the full input.
// ---------------------------------------------------------------------------
template <int S>
__global__ void __launch_bounds__(256) sweep_kernel(const float* __restrict__ pts) {
    const int b = blockIdx.y, chunk = blockIdx.x, tid = threadIdx.x;
    const float* __restrict__ base = pts + (size_t)b * NN * 6;
    __shared__ float3 sc[S];
    __shared__ float s_val[8];
    __shared__ int   s_idx[8];

    recover_centers<S>(base, b, tid, sc);

    float best = -1.0f;
    int bidx = NN;
    const int p0 = chunk * 1024;
    #pragma unroll
    for (int k = 0; k < 4; k++) {
        int p = p0 + k * 256 + tid;
        float3 q = load_xyz(base, p);
        float m = 1e10f;
        #pragma unroll
        for (int t = 0; t < S; t++) {
            float dx = q.x - sc[t].x, dy = q.y - sc[t].y, dz = q.z - sc[t].z;
            float d = dx * dx + dy * dy + dz * dz;
            m = fminf(m, d);
        }
        if (m > best || (m == best && p < bidx)) { best = m; bidx = p; }
    }
    block_argmax256(best, bidx, tid, s_val, s_idx);
    if (tid == 0) {
        g_pval[S - 1][b * 64 + chunk] = best;
        g_pidx[S - 1][b * 64 + chunk] = bidx;
    }
}

// ---------------------------------------------------------------------------
// K4: keep test against all 4 centers -> global bitmask + per-chunk counts.
// grid (32, BB) x 256; 2048 pts/block.
// ---------------------------------------------------------------------------
__global__ void __launch_bounds__(256) keep_kernel(const float* __restrict__ pts) {
    const int b = blockIdx.y, chunk = blockIdx.x, tid = threadIdx.x;
    const float* __restrict__ base = pts + (size_t)b * NN * 6;
    __shared__ float3 sc[4];
    __shared__ int s_c[8];

    recover_centers<4>(base, b, tid, sc);

    const int lane = tid & 31, warp = tid >> 5;
    int cnt = 0;
    const int p0 = chunk * 2048;
    #pragma unroll
    for (int k = 0; k < 8; k++) {
        int p = p0 + k * 256 + tid;
        float3 q = load_xyz(base, p);
        float m = 1e10f;
        #pragma unroll
        for (int t = 0; t < 4; t++) {
            float dx = q.x - sc[t].x, dy = q.y - sc[t].y, dz = q.z - sc[t].z;
            float d = dx * dx + dy * dy + dz * dz;
            m = fminf(m, d);
        }
        bool keep = (sqrtf(m) >= RADIUS);   // == (norm >= 0.2), sqrt monotone
        unsigned w = __ballot_sync(0xffffffffu, keep);
        if (lane == 0) g_bm[b * (NN / 32) + (p >> 5)] = w;
        cnt += keep;
    }
    // block sum
    #pragma unroll
    for (int off = 16; off; off >>= 1) cnt += __shfl_down_sync(0xffffffffu, cnt, off);
    if (lane == 0) s_c[warp] = cnt;
    __syncthreads();
    if (tid == 0) {
        int tot = 0;
        #pragma unroll
        for (int i = 0; i < 8; i++) tot += s_c[i];
        g_cnt[b * 32 + chunk] = tot;
    }
}

// ---------------------------------------------------------------------------
// K5: emit stable kept-index list from bitmask. grid (32, BB) x 64.
// Each thread owns one 32-bit word. Chunk offset computed in-block by
// scanning the batch's 32 chunk counts (tiny, L2-hot).
// ---------------------------------------------------------------------------
__global__ void __launch_bounds__(64) emit_kernel() {
    const int b = blockIdx.y, chunk = blockIdx.x, tid = threadIdx.x;
    __shared__ int s_tot[2];
    __shared__ int s_chunk_off;

    // warp 1: scan chunk counts for this batch
    if (tid >= 32) {
        int lane = tid - 32;
        int v = g_cnt[b * 32 + lane];
        int inc = v;
        #pragma unroll
        for (int off = 1; off < 32; off <<= 1) {
            int n = __shfl_up_sync(0xffffffffu, inc, off);
            if (lane >= off) inc += n;
        }
        if (lane == chunk) s_chunk_off = inc - v;
        if (chunk == 0 && lane == 31) g_numvalid[b] = inc;
    }

    const int word = chunk * 64 + tid;               // word within batch
    unsigned m = g_bm[b * (NN / 32) + word];
    int cnt = __popc(m);

    const int lane = tid & 31, warp = tid >> 5;
    int inc = cnt;
    #pragma unroll
    for (int off = 1; off < 32; off <<= 1) {
        int n = __shfl_up_sync(0xffffffffu, inc, off);
        if (lane >= off) inc += n;
    }
    if (lane == 31) s_tot[warp] = inc;
    __syncthreads();
    int off = s_chunk_off + inc - cnt + (warp ? s_tot[0] : 0);

    int* kept = g_kept + (size_t)b * NN;
    const int base = word * 32;
    while (m) {
        int j = __ffs(m) - 1;
        m &= m - 1;
        kept[off++] = base + j;
    }
}

// ---------------------------------------------------------------------------
// K6: gather output: out[b,j] = points[b, kept[j % nv]]  (zeros if nv==0)
// ---------------------------------------------------------------------------
__global__ void __launch_bounds__(256) gather_kernel(const float* __restrict__ pts,
                                                     float* __restrict__ out) {
    int i = blockIdx.x * blockDim.x + threadIdx.x;
    if (i >= BB * NN) return;
    int b = i >> 16;
    int j = i & (NN - 1);
    int nv = g_numvalid[b];
    float2* o = (float2*)(out + (size_t)i * 6);
    if (nv == 0) {
        float2 z = make_float2(0.f, 0.f);
        o[0] = z; o[1] = z; o[2] = z;
        return;
    }
    int k = (j < nv) ? j : (j % nv);
    int src = g_kept[(size_t)b * NN + k];
    const float2* s = (const float2*)(pts + ((size_t)b * NN + src) * 6);
    float2 a0 = s[0], a1 = s[1], a2 = s[2];
    o[0] = a0; o[1] = a1; o[2] = a2;
}

extern "C" void kernel_launch(void* const* d_in, const int* in_sizes, int n_in,
                              void* d_out, int out_size) {
    const float* pts = (const float*)d_in[0];
    float* out = (float*)d_out;
    (void)in_sizes; (void)n_in; (void)out_size;

    sweep_kernel<1><<<dim3(64, BB), 256>>>(pts);
    sweep_kernel<2><<<dim3(64, BB), 256>>>(pts);
    sweep_kernel<3><<<dim3(64, BB), 256>>>(pts);
    keep_kernel<<<dim3(32, BB), 256>>>(pts);
    emit_kernel<<<dim3(32, BB), 64>>>();
    gather_kernel<<<(BB * NN + 255) / 256, 256>>>(pts, out);
}

// round 8
// speedup vs baseline: 1.1976x; 1.1976x over previous
#include <cuda_runtime.h>

#define BB 64
#define NN 65536
#define RADIUS 0.2f

// Scratch (__device__ globals per allocation-free rule)
__device__ float    g_x[(size_t)BB * NN];           // SoA packed xyz, 3x16 MB
__device__ float    g_y[(size_t)BB * NN];
__device__ float    g_z[(size_t)BB * NN];
__device__ float    g_pval[3][BB * 64];             // argmax partials per FPS step
__device__ int      g_pidx[3][BB * 64];
__device__ unsigned g_bm[BB * (NN / 32)];           // keep bitmask, 512 KB
__device__ int      g_cnt[BB * 32];                 // per-chunk keep counts
__device__ int      g_numvalid[BB];

// ---------------------------------------------------------------------------
// Argmax helpers: larger value wins, tie -> smaller index (jnp.argmax semantics)
// ---------------------------------------------------------------------------
__device__ __forceinline__ void warp_argmax(float& v, int& i) {
    #pragma unroll
    for (int off = 16; off; off >>= 1) {
        float ov = __shfl_down_sync(0xffffffffu, v, off);
        int   oi = __shfl_down_sync(0xffffffffu, i, off);
        if (ov > v || (ov == v && oi < i)) { v = ov; i = oi; }
    }
}

// 256-thread (8-warp) block argmax; result valid in thread 0.
__device__ __forceinline__ void block_argmax256(float& v, int& i, int tid,
                                                float* s_val, int* s_idx) {
    warp_argmax(v, i);
    if ((tid & 31) == 0) { s_val[tid >> 5] = v; s_idx[tid >> 5] = i; }
    __syncthreads();
    if (tid < 32) {
        v = (tid < 8) ? s_val[tid] : -2.0f;
        i = (tid < 8) ? s_idx[tid] : NN;
        warp_argmax(v, i);
    }
}

// Reduce 64 partials of set j -> argmax (lane 0 of calling warp holds result).
__device__ __forceinline__ void reduce_partials(int j, int b, int lane,
                                                float& v, int& i) {
    v = g_pval[j][b * 64 + lane];
    i = g_pidx[j][b * 64 + lane];
    float v2 = g_pval[j][b * 64 + 32 + lane];
    int   i2 = g_pidx[j][b * 64 + 32 + lane];
    if (v2 > v || (v2 == v && i2 < i)) { v = v2; i = i2; }
    warp_argmax(v, i);
}

// Recover centers 1..S-1 from partial sets (center 0 = point 0 of batch).
template <int S>
__device__ __forceinline__ void recover_centers(const float* __restrict__ pts,
                                                int b, int tid, float3* sc) {
    const size_t bb = (size_t)b * NN;
    if (tid == 0) {
        const float* q = pts + bb * 6;
        sc[0] = make_float3(q[0], q[1], q[2]);
    }
    if (tid < 32) {
        #pragma unroll
        for (int j = 0; j < S - 1; j++) {
            float v; int i;
            reduce_partials(j, b, tid, v, i);
            if (tid == 0) sc[j + 1] = make_float3(g_x[bb + i], g_y[bb + i], g_z[bb + i]);
        }
    }
    __syncthreads();
}

// ---------------------------------------------------------------------------
// K1: read raw pts, write SoA xyz, compute dist-to-center0 argmax partials.
// grid (64, BB) x 256; 1024 pts/block.
// ---------------------------------------------------------------------------
__global__ void __launch_bounds__(256) sweep1_pack_kernel(const float* __restrict__ pts) {
    const int b = blockIdx.y, chunk = blockIdx.x, tid = threadIdx.x;
    const float* __restrict__ base = pts + (size_t)b * NN * 6;
    const float cx = __ldg(base), cy = __ldg(base + 1), cz = __ldg(base + 2);
    const size_t bb = (size_t)b * NN;

    __shared__ float s_val[8];
    __shared__ int   s_idx[8];

    float best = -1.0f;
    int bidx = NN;
    const int p0 = chunk * 1024;
    #pragma unroll
    for (int k = 0; k < 4; k++) {
        int p = p0 + k * 256 + tid;
        const float* q = base + (size_t)p * 6;
        float2 xy = *(const float2*)q;
        float z = q[2];
        g_x[bb + p] = xy.x;
        g_y[bb + p] = xy.y;
        g_z[bb + p] = z;
        float dx = xy.x - cx, dy = xy.y - cy, dz = z - cz;
        float d = dx * dx + dy * dy + dz * dz;
        if (d > best || (d == best && p < bidx)) { best = d; bidx = p; }
    }
    block_argmax256(best, bidx, tid, s_val, s_idx);
    if (tid == 0) {
        g_pval[0][b * 64 + chunk] = best;
        g_pidx[0][b * 64 + chunk] = bidx;
    }
}

// ---------------------------------------------------------------------------
// K2/K3: FPS sweep with S known centers (S=2,3) reading SoA.
// grid (64, BB) x 256; 1024 pts/block.
// ---------------------------------------------------------------------------
template <int S>
__global__ void __launch_bounds__(256) sweep_kernel(const float* __restrict__ pts) {
    const int b = blockIdx.y, chunk = blockIdx.x, tid = threadIdx.x;
    const size_t bb = (size_t)b * NN;
    __shared__ float3 sc[S];
    __shared__ float s_val[8];
    __shared__ int   s_idx[8];

    recover_centers<S>(pts, b, tid, sc);

    float best = -1.0f;
    int bidx = NN;
    const int p0 = chunk * 1024;
    #pragma unroll
    for (int k = 0; k < 4; k++) {
        int p = p0 + k * 256 + tid;
        float qx = g_x[bb + p], qy = g_y[bb + p], qz = g_z[bb + p];
        float m = 1e10f;
        #pragma unroll
        for (int t = 0; t < S; t++) {
            float dx = qx - sc[t].x, dy = qy - sc[t].y, dz = qz - sc[t].z;
            float d = dx * dx + dy * dy + dz * dz;
            m = fminf(m, d);
        }
        if (m > best || (m == best && p < bidx)) { best = m; bidx = p; }
    }
    block_argmax256(best, bidx, tid, s_val, s_idx);
    if (tid == 0) {
        g_pval[S - 1][b * 64 + chunk] = best;
        g_pidx[S - 1][b * 64 + chunk] = bidx;
    }
}

// ---------------------------------------------------------------------------
// K4: keep test against 4 centers -> bitmask + per-chunk counts.
// grid (32, BB) x 256; 2048 pts/block.
// ---------------------------------------------------------------------------
__global__ void __launch_bounds__(256) keep_kernel(const float* __restrict__ pts) {
    const int b = blockIdx.y, chunk = blockIdx.x, tid = threadIdx.x;
    const size_t bb = (size_t)b * NN;
    __shared__ float3 sc[4];
    __shared__ int s_c[8];

    recover_centers<4>(pts, b, tid, sc);

    const int lane = tid & 31, warp = tid >> 5;
    int cnt = 0;
    const int p0 = chunk * 2048;
    #pragma unroll
    for (int k = 0; k < 8; k++) {
        int p = p0 + k * 256 + tid;
        float qx = g_x[bb + p], qy = g_y[bb + p], qz = g_z[bb + p];
        float m = 1e10f;
        #pragma unroll
        for (int t = 0; t < 4; t++) {
            float dx = qx - sc[t].x, dy = qy - sc[t].y, dz = qz - sc[t].z;
            float d = dx * dx + dy * dy + dz * dz;
            m = fminf(m, d);
        }
        bool keep = (sqrtf(m) >= RADIUS);   // == (norm >= 0.2), sqrt monotone
        unsigned w = __ballot_sync(0xffffffffu, keep);
        if (lane == 0) g_bm[b * (NN / 32) + (p >> 5)] = w;
        cnt += keep;
    }
    #pragma unroll
    for (int off = 16; off; off >>= 1) cnt += __shfl_down_sync(0xffffffffu, cnt, off);
    if (lane == 0) s_c[warp] = cnt;
    __syncthreads();
    if (tid == 0) {
        int tot = 0;
        #pragma unroll
        for (int i = 0; i < 8; i++) tot += s_c[i];
        g_cnt[b * 32 + chunk] = tot;
    }
}

// ---------------------------------------------------------------------------
// K5: scatter kept points directly to out[rank]. grid (32, BB) x 256.
// Rank = batch-stable prefix (chunk offset + word prefix + bit prefix).
// Also writes g_numvalid (from chunk-0 block's scan).
// ---------------------------------------------------------------------------
__global__ void __launch_bounds__(256) scatter_kernel(const float* __restrict__ pts,
                                                      float* __restrict__ out) {
    const int b = blockIdx.y, chunk = blockIdx.x, tid = threadIdx.x;
    __shared__ unsigned s_w[64];
    __shared__ int s_wpref[64];
    __shared__ int s_wtot[2];
    __shared__ int s_chunk_off;

    // warp 0: exclusive scan of the batch's 32 chunk counts
    if (tid < 32) {
        int v = g_cnt[b * 32 + tid];
        int inc = v;
        #pragma unroll
        for (int off = 1; off < 32; off <<= 1) {
            int n = __shfl_up_sync(0xffffffffu, inc, off);
            if (tid >= off) inc += n;
        }
        if (tid == chunk) s_chunk_off = inc - v;
        if (chunk == 0 && tid == 31) g_numvalid[b] = inc;
    }
    // load this chunk's 64 bitmask words
    if (tid >= 64 && tid < 128) s_w[tid - 64] = g_bm[b * (NN / 32) + chunk * 64 + (tid - 64)];
    __syncthreads();

    // exclusive word-prefix over 64 popcounts (warps 0,1)
    if (tid < 64) {
        int pc = __popc(s_w[tid]);
        int lane = tid & 31;
        int inc = pc;
        #pragma unroll
        for (int off = 1; off < 32; off <<= 1) {
            int n = __shfl_up_sync(0xffffffffu, inc, off);
            if (lane >= off) inc += n;
        }
        s_wpref[tid] = inc - pc;
        if (lane == 31) s_wtot[tid >> 5] = inc;
    }
    __syncthreads();
    if (tid >= 32 && tid < 64) s_wpref[tid] += s_wtot[0];
    __syncthreads();

    const float* __restrict__ base = pts + (size_t)b * NN * 6;
    float* __restrict__ obase = out + (size_t)b * NN * 6;
    const int p0 = chunk * 2048;
    #pragma unroll
    for (int k = 0; k < 8; k++) {
        int pl = k * 256 + tid;                 // local point 0..2047
        unsigned word = s_w[pl >> 5];
        int bit = pl & 31;
        if ((word >> bit) & 1u) {
            int rank = s_chunk_off + s_wpref[pl >> 5] + __popc(word & ((1u << bit) - 1u));
            const float2* s = (const float2*)(base + (size_t)(p0 + pl) * 6);
            float2 a0 = s[0], a1 = s[1], a2 = s[2];
            float2* o = (float2*)(obase + (size_t)rank * 6);
            o[0] = a0; o[1] = a1; o[2] = a2;
        }
    }
}

// ---------------------------------------------------------------------------
// K6: tail fill: rows j >= nv copy from out[j % nv]; nv==0 -> zeros.
// Source rows were written by K5 (previous kernel) — no hazard.
// ---------------------------------------------------------------------------
__global__ void __launch_bounds__(256) tail_kernel(float* __restrict__ out) {
    int i = blockIdx.x * blockDim.x + threadIdx.x;
    if (i >= BB * NN) return;
    int b = i >> 16;
    int j = i & (NN - 1);
    int nv = g_numvalid[b];
    float* __restrict__ obase = out + (size_t)b * NN * 6;
    if (nv == 0) {
        float2 z = make_float2(0.f, 0.f);
        float2* o = (float2*)(obase + (size_t)j * 6);
        o[0] = z; o[1] = z; o[2] = z;
        return;
    }
    if (j < nv) return;
    int k = j % nv;
    const float2* s = (const float2*)(obase + (size_t)k * 6);
    float2 a0 = s[0], a1 = s[1], a2 = s[2];
    float2* o = (float2*)(obase + (size_t)j * 6);
    o[0] = a0; o[1] = a1; o[2] = a2;
}

extern "C" void kernel_launch(void* const* d_in, const int* in_sizes, int n_in,
                              void* d_out, int out_size) {
    const float* pts = (const float*)d_in[0];
    float* out = (float*)d_out;
    (void)in_sizes; (void)n_in; (void)out_size;

    sweep1_pack_kernel<<<dim3(64, BB), 256>>>(pts);
    sweep_kernel<2><<<dim3(64, BB), 256>>>(pts);
    sweep_kernel<3><<<dim3(64, BB), 256>>>(pts);
    keep_kernel<<<dim3(32, BB), 256>>>(pts);
    scatter_kernel<<<dim3(32, BB), 256>>>(pts, out);
    tail_kernel<<<(BB * NN + 255) / 256, 256>>>(out);
}

// round 9
// speedup vs baseline: 1.2471x; 1.0413x over previous
#include <cuda_runtime.h>

#define BB 64
#define NN 65536
#define RADIUS 0.2f

// Scratch (__device__ globals per allocation-free rule)
__device__ float    g_x[(size_t)BB * NN];           // SoA packed xyz, 3x16 MB
__device__ float    g_y[(size_t)BB * NN];
__device__ float    g_z[(size_t)BB * NN];
__device__ float    g_pval[3][BB * 64];             // argmax partials per FPS step
__device__ int      g_pidx[3][BB * 64];
__device__ unsigned g_bm[BB * (NN / 32)];           // keep bitmask, 512 KB
__device__ int      g_cnt[BB * 32];                 // per-chunk keep counts
__device__ int      g_numvalid[BB];

// ---------------------------------------------------------------------------
// Argmax helpers: larger value wins, tie -> smaller index (jnp.argmax semantics)
// ---------------------------------------------------------------------------
__device__ __forceinline__ void warp_argmax(float& v, int& i) {
    #pragma unroll
    for (int off = 16; off; off >>= 1) {
        float ov = __shfl_down_sync(0xffffffffu, v, off);
        int   oi = __shfl_down_sync(0xffffffffu, i, off);
        if (ov > v || (ov == v && oi < i)) { v = ov; i = oi; }
    }
}

// 256-thread (8-warp) block argmax; result valid in thread 0.
__device__ __forceinline__ void block_argmax256(float& v, int& i, int tid,
                                                float* s_val, int* s_idx) {
    warp_argmax(v, i);
    if ((tid & 31) == 0) { s_val[tid >> 5] = v; s_idx[tid >> 5] = i; }
    __syncthreads();
    if (tid < 32) {
        v = (tid < 8) ? s_val[tid] : -2.0f;
        i = (tid < 8) ? s_idx[tid] : NN;
        warp_argmax(v, i);
    }
}

// Reduce 64 partials of set j -> argmax (lane 0 of calling warp holds result).
__device__ __forceinline__ void reduce_partials(int j, int b, int lane,
                                                float& v, int& i) {
    v = g_pval[j][b * 64 + lane];
    i = g_pidx[j][b * 64 + lane];
    float v2 = g_pval[j][b * 64 + 32 + lane];
    int   i2 = g_pidx[j][b * 64 + 32 + lane];
    if (v2 > v || (v2 == v && i2 < i)) { v = v2; i = i2; }
    warp_argmax(v, i);
}

// Recover centers 1..S-1 from partial sets (center 0 = point 0 of batch).
template <int S>
__device__ __forceinline__ void recover_centers(const float* __restrict__ pts,
                                                int b, int tid, float3* sc) {
    const size_t bb = (size_t)b * NN;
    if (tid == 0) {
        const float* q = pts + bb * 6;
        sc[0] = make_float3(q[0], q[1], q[2]);
    }
    if (tid < 32) {
        #pragma unroll
        for (int j = 0; j < S - 1; j++) {
            float v; int i;
            reduce_partials(j, b, tid, v, i);
            if (tid == 0) sc[j + 1] = make_float3(g_x[bb + i], g_y[bb + i], g_z[bb + i]);
        }
    }
    __syncthreads();
}

// ---------------------------------------------------------------------------
// K1: read raw pts, write SoA xyz, compute dist-to-center0 argmax partials.
// grid (64, BB) x 256; 1024 pts/block. Loads batched up front for MLP.
// ---------------------------------------------------------------------------
__global__ void __launch_bounds__(256) sweep1_pack_kernel(const float* __restrict__ pts) {
    const int b = blockIdx.y, chunk = blockIdx.x, tid = threadIdx.x;
    const float* __restrict__ base = pts + (size_t)b * NN * 6;
    const float cx = __ldg(base), cy = __ldg(base + 1), cz = __ldg(base + 2);
    const size_t bb = (size_t)b * NN;

    __shared__ float s_val[8];
    __shared__ int   s_idx[8];

    const int p0 = chunk * 1024;
    float qx[4], qy[4], qz[4];
    // phase 1: issue all 8 loads back-to-back (float2 + float per point)
    #pragma unroll
    for (int k = 0; k < 4; k++) {
        const float* q = base + (size_t)(p0 + k * 256 + tid) * 6;
        float2 xy = *(const float2*)q;
        qx[k] = xy.x; qy[k] = xy.y; qz[k] = q[2];
    }
    // phase 2: store SoA + argmax
    float best = -1.0f;
    int bidx = NN;
    #pragma unroll
    for (int k = 0; k < 4; k++) {
        int p = p0 + k * 256 + tid;
        g_x[bb + p] = qx[k];
        g_y[bb + p] = qy[k];
        g_z[bb + p] = qz[k];
        float dx = qx[k] - cx, dy = qy[k] - cy, dz = qz[k] - cz;
        float d = dx * dx + dy * dy + dz * dz;
        if (d > best || (d == best && p < bidx)) { best = d; bidx = p; }
    }
    block_argmax256(best, bidx, tid, s_val, s_idx);
    if (tid == 0) {
        g_pval[0][b * 64 + chunk] = best;
        g_pidx[0][b * 64 + chunk] = bidx;
    }
}

// ---------------------------------------------------------------------------
// K2/K3: FPS sweep with S known centers (S=2,3) reading SoA. Batched loads.
// grid (64, BB) x 256; 1024 pts/block.
// ---------------------------------------------------------------------------
template <int S>
__global__ void __launch_bounds__(256) sweep_kernel(const float* __restrict__ pts) {
    const int b = blockIdx.y, chunk = blockIdx.x, tid = threadIdx.x;
    const size_t bb = (size_t)b * NN;
    __shared__ float3 sc[S];
    __shared__ float s_val[8];
    __shared__ int   s_idx[8];

    recover_centers<S>(pts, b, tid, sc);

    const int p0 = chunk * 1024;
    float qx[4], qy[4], qz[4];
    #pragma unroll
    for (int k = 0; k < 4; k++) {
        size_t idx = bb + p0 + k * 256 + tid;
        qx[k] = g_x[idx]; qy[k] = g_y[idx]; qz[k] = g_z[idx];
    }
    float best = -1.0f;
    int bidx = NN;
    #pragma unroll
    for (int k = 0; k < 4; k++) {
        int p = p0 + k * 256 + tid;
        float m = 1e10f;
        #pragma unroll
        for (int t = 0; t < S; t++) {
            float dx = qx[k] - sc[t].x, dy = qy[k] - sc[t].y, dz = qz[k] - sc[t].z;
            float d = dx * dx + dy * dy + dz * dz;
            m = fminf(m, d);
        }
        if (m > best || (m == best && p < bidx)) { best = m; bidx = p; }
    }
    block_argmax256(best, bidx, tid, s_val, s_idx);
    if (tid == 0) {
        g_pval[S - 1][b * 64 + chunk] = best;
        g_pidx[S - 1][b * 64 + chunk] = bidx;
    }
}

// ---------------------------------------------------------------------------
// K4: keep test against 4 centers -> bitmask + per-chunk counts.
// grid (32, BB) x 256; 2048 pts/block. All 24 loads issued before any ballot.
// ---------------------------------------------------------------------------
__global__ void __launch_bounds__(256) keep_kernel(const float* __restrict__ pts) {
    const int b = blockIdx.y, chunk = blockIdx.x, tid = threadIdx.x;
    const size_t bb = (size_t)b * NN;
    __shared__ float3 sc[4];
    __shared__ int s_c[8];

    recover_centers<4>(pts, b, tid, sc);

    const int lane = tid & 31, warp = tid >> 5;
    const int p0 = chunk * 2048;

    // phase 1: 24 independent loads, no sync in between -> MLP ~24
    float qx[8], qy[8], qz[8];
    #pragma unroll
    for (int k = 0; k < 8; k++) {
        size_t idx = bb + p0 + k * 256 + tid;
        qx[k] = g_x[idx]; qy[k] = g_y[idx]; qz[k] = g_z[idx];
    }

    // phase 2: compute + ballot + store
    int cnt = 0;
    #pragma unroll
    for (int k = 0; k < 8; k++) {
        int p = p0 + k * 256 + tid;
        float m = 1e10f;
        #pragma unroll
        for (int t = 0; t < 4; t++) {
            float dx = qx[k] - sc[t].x, dy = qy[k] - sc[t].y, dz = qz[k] - sc[t].z;
            float d = dx * dx + dy * dy + dz * dz;
            m = fminf(m, d);
        }
        bool keep = (sqrtf(m) >= RADIUS);   // == (norm >= 0.2), sqrt monotone
        unsigned w = __ballot_sync(0xffffffffu, keep);
        if (lane == 0) g_bm[b * (NN / 32) + (p >> 5)] = w;
        cnt += keep;
    }
    #pragma unroll
    for (int off = 16; off; off >>= 1) cnt += __shfl_down_sync(0xffffffffu, cnt, off);
    if (lane == 0) s_c[warp] = cnt;
    __syncthreads();
    if (tid == 0) {
        int tot = 0;
        #pragma unroll
        for (int i = 0; i < 8; i++) tot += s_c[i];
        g_cnt[b * 32 + chunk] = tot;
    }
}

// ---------------------------------------------------------------------------
// K5: scatter kept points directly to out[rank]. grid (32, BB) x 256.
// Rank = batch-stable prefix (chunk offset + word prefix + bit prefix).
// ---------------------------------------------------------------------------
__global__ void __launch_bounds__(256) scatter_kernel(const float* __restrict__ pts,
                                                      float* __restrict__ out) {
    const int b = blockIdx.y, chunk = blockIdx.x, tid = threadIdx.x;
    __shared__ unsigned s_w[64];
    __shared__ int s_wpref[64];
    __shared__ int s_wtot[2];
    __shared__ int s_chunk_off;

    // warp 0: exclusive scan of the batch's 32 chunk counts
    if (tid < 32) {
        int v = g_cnt[b * 32 + tid];
        int inc = v;
        #pragma unroll
        for (int off = 1; off < 32; off <<= 1) {
            int n = __shfl_up_sync(0xffffffffu, inc, off);
            if (tid >= off) inc += n;
        }
        if (tid == chunk) s_chunk_off = inc - v;
        if (chunk == 0 && tid == 31) g_numvalid[b] = inc;
    }
    // load this chunk's 64 bitmask words
    if (tid >= 64 && tid < 128) s_w[tid - 64] = g_bm[b * (NN / 32) + chunk * 64 + (tid - 64)];
    __syncthreads();

    // exclusive word-prefix over 64 popcounts (warps 0,1)
    if (tid < 64) {
        int pc = __popc(s_w[tid]);
        int lane = tid & 31;
        int inc = pc;
        #pragma unroll
        for (int off = 1; off < 32; off <<= 1) {
            int n = __shfl_up_sync(0xffffffffu, inc, off);
            if (lane >= off) inc += n;
        }
        s_wpref[tid] = inc - pc;
        if (lane == 31) s_wtot[tid >> 5] = inc;
    }
    __syncthreads();
    if (tid >= 32 && tid < 64) s_wpref[tid] += s_wtot[0];
    __syncthreads();

    const float* __restrict__ base = pts + (size_t)b * NN * 6;
    float* __restrict__ obase = out + (size_t)b * NN * 6;
    const int p0 = chunk * 2048;
    #pragma unroll
    for (int k = 0; k < 8; k++) {
        int pl = k * 256 + tid;                 // local point 0..2047
        unsigned word = s_w[pl >> 5];
        int bit = pl & 31;
        if ((word >> bit) & 1u) {
            int rank = s_chunk_off + s_wpref[pl >> 5] + __popc(word & ((1u << bit) - 1u));
            const float2* s = (const float2*)(base + (size_t)(p0 + pl) * 6);
            float2 a0 = s[0], a1 = s[1], a2 = s[2];
            float2* o = (float2*)(obase + (size_t)rank * 6);
            o[0] = a0; o[1] = a1; o[2] = a2;
        }
    }
}

// ---------------------------------------------------------------------------
// K6: tail fill: rows j >= nv copy from out[j % nv]; nv==0 -> zeros.
// Source rows were written by K5 (previous kernel) — no hazard.
// ---------------------------------------------------------------------------
__global__ void __launch_bounds__(256) tail_kernel(float* __restrict__ out) {
    int i = blockIdx.x * blockDim.x + threadIdx.x;
    if (i >= BB * NN) return;
    int b = i >> 16;
    int j = i & (NN - 1);
    int nv = g_numvalid[b];
    float* __restrict__ obase = out + (size_t)b * NN * 6;
    if (nv == 0) {
        float2 z = make_float2(0.f, 0.f);
        float2* o = (float2*)(obase + (size_t)j * 6);
        o[0] = z; o[1] = z; o[2] = z;
        return;
    }
    if (j < nv) return;
    int k = j % nv;
    const float2* s = (const float2*)(obase + (size_t)k * 6);
    float2 a0 = s[0], a1 = s[1], a2 = s[2];
    float2* o = (float2*)(obase + (size_t)j * 6);
    o[0] = a0; o[1] = a1; o[2] = a2;
}

extern "C" void kernel_launch(void* const* d_in, const int* in_sizes, int n_in,
                              void* d_out, int out_size) {
    const float* pts = (const float*)d_in[0];
    float* out = (float*)d_out;
    (void)in_sizes; (void)n_in; (void)out_size;

    sweep1_pack_kernel<<<dim3(64, BB), 256>>>(pts);
    sweep_kernel<2><<<dim3(64, BB), 256>>>(pts);
    sweep_kernel<3><<<dim3(64, BB), 256>>>(pts);
    keep_kernel<<<dim3(32, BB), 256>>>(pts);
    scatter_kernel<<<dim3(32, BB), 256>>>(pts, out);
    tail_kernel<<<(BB * NN + 255) / 256, 256>>>(out);
}